// round 11
// baseline (speedup 1.0000x reference)
#include <cuda_runtime.h>

// SCE loss: softmax over C=128, signed per-(class,bin) histogram of
// p - onehot, then sum |.| / (B*C).
// Round 11: back to 4 classes/lane (R5 layout, 1 row/warp-iter, no tail),
// two REGISTER bins (bin0: p<=1/15, bin1: 1/15<p<=2/15) in 30 regs ->
// occupancy 8; slow path only for p>2/15 (warp rate ~5%). Label -1:
// register byte-counter when label is in bin0 (99.6%), one atomic when in
// bin1, slow path handles >2/15. No per-row atomics in the hot path.

namespace {
constexpr int kC       = 128;
constexpr int kBins    = 15;
constexpr int kSegs    = kC * kBins;   // 1920
constexpr int kBlocks  = 1184;
constexpr int kThreads = 256;
}

__device__ float    g_seg[kSegs];   // zero at load; last block re-zeroes
__device__ unsigned g_count;        // zero at load; last block re-zeroes

__global__ void __launch_bounds__(kThreads, 8)
sce_kernel(const float* __restrict__ logits, const int* __restrict__ labels,
           int B, float* __restrict__ out, float scale)
{
    __shared__ float s[kSegs];
    for (int i = threadIdx.x; i < kSegs; i += blockDim.x) s[i] = 0.0f;
    __syncthreads();

    const int lane = threadIdx.x & 31;
    const int wpb  = blockDim.x >> 5;
    const int gw   = blockIdx.x * wpb + (threadIdx.x >> 5);
    const int nw   = gridDim.x * wpb;
    const int c0   = lane << 2;          // classes c0..c0+3 (contiguous)

    float bin0[4] = {0,0,0,0};           // p <= 1/15
    float bin1[4] = {0,0,0,0};           // 1/15 < p <= 2/15 (+ provisional)
    int   cnt     = 0;                   // packed byte counts: label in bin0

    const float* rp = logits + (size_t)gw * kC + c0;
    const int*   lp = labels + gw;
    const size_t rstep = (size_t)nw * kC;

    for (int row = gw; row < B; row += nw, rp += rstep, lp += nw) {
        const int lab = __ldg(lp);
        const float4 v = __ldg(reinterpret_cast<const float4*>(rp));

        float e[4];
        e[0] = __expf(v.x); e[1] = __expf(v.y);
        e[2] = __expf(v.z); e[3] = __expf(v.w);

        float sm = (e[0] + e[1]) + (e[2] + e[3]);
        #pragma unroll
        for (int o = 16; o > 0; o >>= 1)
            sm += __shfl_xor_sync(0xffffffffu, sm, o);

        const float inv = __fdividef(1.0f, sm);
        const float t1  = sm * (1.0f / 15.0f);   // e > t1 <=> p > 1/15
        const float t2  = t1 + t1;               // e > t2 <=> p > 2/15

        // branchless two-register binning (elements > t2 land in bin1
        // provisionally; the rare slow path moves them out)
        #pragma unroll
        for (int j = 0; j < 4; j++) {
            if (e[j] > t1) bin1[j] = fmaf(e[j], inv, bin1[j]);
            else           bin0[j] = fmaf(e[j], inv, bin0[j]);
        }

        // label -1: owner lane only (1/32). esel = label element's exp.
        const bool match = (lane == (lab >> 2));
        if (match) {
            const float m0   = (lab & 1) ? e[1] : e[0];
            const float m1   = (lab & 1) ? e[3] : e[2];
            const float esel = (lab & 2) ? m1 : m0;
            if (esel <= t1)      cnt += 1 << ((lab & 3) * 8);  // register
            else if (esel <= t2) atomicAdd(&s[lab * kBins + 1], -1.0f);
            // esel > t2: slow path below adds p-1 directly
        }

        const float mx = fmaxf(fmaxf(e[0], e[1]), fmaxf(e[2], e[3]));
        if (mx > t2) {                       // ~5% of warp-iterations
            #pragma unroll
            for (int j = 0; j < 4; j++) {
                if (e[j] > t2) {
                    const float p = e[j] * inv;
                    int k = __float2int_ru(p * 15.0f) - 1;   // >= 2 here
                    k = min(k, kBins - 1);
                    const bool isl = match && ((lab & 3) == j);
                    atomicAdd(&s[(c0 + j) * kBins + k], isl ? p - 1.0f : p);
                    bin1[j] -= p;            // was provisionally in bin1
                }
            }
        }
    }

    // flush register accumulators into the block histogram
    #pragma unroll
    for (int j = 0; j < 4; j++) {
        const float lc = (float)((cnt >> (8 * j)) & 0xff);
        atomicAdd(&s[(c0 + j) * kBins + 0], bin0[j] - lc);
        atomicAdd(&s[(c0 + j) * kBins + 1], bin1[j]);
    }
    __syncthreads();

    // block histogram -> global
    for (int i = threadIdx.x; i < kSegs; i += blockDim.x) {
        const float v = s[i];
        if (v != 0.0f) atomicAdd(&g_seg[i], v);
    }

    // last-block finalize
    __shared__ bool isLast;
    __threadfence();
    if (threadIdx.x == 0)
        isLast = (atomicAdd(&g_count, 1u) == (unsigned)gridDim.x - 1u);
    __syncthreads();
    if (!isLast) return;

    __shared__ float red[32];
    float acc = 0.0f;
    for (int i = threadIdx.x; i < kSegs; i += blockDim.x) {
        acc += fabsf(__ldcg(&g_seg[i]));
        g_seg[i] = 0.0f;                   // reset for next replay
    }
    #pragma unroll
    for (int o = 16; o > 0; o >>= 1)
        acc += __shfl_xor_sync(0xffffffffu, acc, o);
    const int w = threadIdx.x >> 5;
    if (lane == 0) red[w] = acc;
    __syncthreads();
    if (w == 0) {
        const int nwarps = blockDim.x >> 5;
        acc = (lane < nwarps) ? red[lane] : 0.0f;
        #pragma unroll
        for (int o = 16; o > 0; o >>= 1)
            acc += __shfl_xor_sync(0xffffffffu, acc, o);
        if (threadIdx.x == 0) {
            out[0]  = acc * scale;
            g_count = 0u;                  // reset for next replay
        }
    }
}

extern "C" void kernel_launch(void* const* d_in, const int* in_sizes, int n_in,
                              void* d_out, int out_size) {
    const float* logits = (const float*)d_in[0];
    const int*   labels = (const int*)d_in[1];
    const int B = in_sizes[1];
    const float scale = 1.0f / ((float)B * (float)kC);
    sce_kernel<<<kBlocks, kThreads>>>(logits, labels, B, (float*)d_out, scale);
}

// round 12
// speedup vs baseline: 1.0275x; 1.0275x over previous
#include <cuda_runtime.h>

// SCE loss: softmax over C=128, signed per-(class,bin) histogram of
// p - onehot, then sum |.| / (B*C).
// Round 12: R8 base (half-warp rows, 8 classes/lane split layout, single
// register bin0 + t1 slow path) + register ping-pong PREFETCH: iteration
// k+1's loads are issued before iteration k's compute, removing the
// exposed LDG->exp scoreboard stall. bounds(256,6), grid 888 (exact wave).

namespace {
constexpr int kC       = 128;
constexpr int kBins    = 15;
constexpr int kSegs    = kC * kBins;   // 1920
constexpr int kBlocks  = 888;          // 6 blocks/SM x 148 SMs
constexpr int kThreads = 256;
}

__device__ float    g_seg[kSegs];   // zero at load; last block re-zeroes
__device__ unsigned g_count;        // zero at load; last block re-zeroes

__global__ void __launch_bounds__(kThreads, 6)
sce_kernel(const float* __restrict__ logits, const int* __restrict__ labels,
           int B, float* __restrict__ out, float scale)
{
    __shared__ float s[kSegs];
    for (int i = threadIdx.x; i < kSegs; i += blockDim.x) s[i] = 0.0f;
    __syncthreads();

    const int lane = threadIdx.x & 31;
    const int wpb  = blockDim.x >> 5;
    const int gw   = blockIdx.x * wpb + (threadIdx.x >> 5);
    const int nw   = gridDim.x * wpb;
    const int h    = lane >> 4;          // which row of the pair
    const int L    = lane & 15;
    const int c0   = L << 2;             // classes c0..c0+3 and 64+c0..64+c0+3

    float bin0[8] = {0,0,0,0,0,0,0,0};

    int row0 = gw * 2;
    const float* rp = logits + (size_t)(row0 + h) * kC + c0;
    const int*   lp = labels + row0 + h;
    const size_t rstep = (size_t)nw * 2 * kC;
    const int    lstep = nw * 2;

    if (row0 + 1 < B) {
        // prologue: load iteration 0
        float4 va = __ldg(reinterpret_cast<const float4*>(rp));
        float4 vb = __ldg(reinterpret_cast<const float4*>(rp + 64));
        int    lab = __ldg(lp);

        for (;;) {
            // ---- prefetch next iteration (clamped; discarded at the end) --
            const int  nrow = row0 + lstep;
            const bool more = (nrow + 1 < B);
            const float* nrp = more ? (rp + rstep) : rp;
            const int*   nlp = more ? (lp + lstep) : lp;
            const float4 nva = __ldg(reinterpret_cast<const float4*>(nrp));
            const float4 nvb = __ldg(reinterpret_cast<const float4*>(nrp + 64));
            const int    nlab = __ldg(nlp);

            // ---- process current iteration (R8 body) ---------------------
            float e[8];
            e[0] = __expf(va.x); e[1] = __expf(va.y);
            e[2] = __expf(va.z); e[3] = __expf(va.w);
            e[4] = __expf(vb.x); e[5] = __expf(vb.y);
            e[6] = __expf(vb.z); e[7] = __expf(vb.w);

            float sm = ((e[0] + e[1]) + (e[2] + e[3]))
                     + ((e[4] + e[5]) + (e[6] + e[7]));
            #pragma unroll
            for (int o = 8; o > 0; o >>= 1)      // 4-level, 16-lane half
                sm += __shfl_xor_sync(0xffffffffu, sm, o);

            const float inv    = __fdividef(1.0f, sm);
            const float thresh = sm * (1.0f / 15.0f);  // e>th <=> p>1/15

            #pragma unroll
            for (int j = 0; j < 8; j++)
                bin0[j] = fmaf(e[j], inv, bin0[j]);     // provisional bin 0

            // label -1: exactly one lane per row matches (predicated ATOMS)
            const int  r    = lab & 63;
            const int  jlab = (lab >> 6 << 2) | (r & 3);
            const bool match = (L == (r >> 2));
            if (match) atomicAdd(&s[lab * kBins], -1.0f);

            const float m01 = fmaxf(fmaxf(e[0], e[1]), fmaxf(e[2], e[3]));
            const float m23 = fmaxf(fmaxf(e[4], e[5]), fmaxf(e[6], e[7]));
            if (fmaxf(m01, m23) > thresh) {      // fix up p > 1/15 elements
                #pragma unroll
                for (int j = 0; j < 8; j++) {
                    if (e[j] > thresh) {
                        const float p = e[j] * inv;
                        int k = __float2int_ru(p * 15.0f) - 1;
                        k = min(k, kBins - 1);
                        float add = p;
                        if (match && j == jlab) {
                            add = p - 1.0f;
                            atomicAdd(&s[lab * kBins], 1.0f);
                        }
                        const int cls = (j < 4) ? (c0 + j) : (64 + c0 + j - 4);
                        atomicAdd(&s[cls * kBins + k], add);
                        bin0[j] -= p;
                    }
                }
            }

            if (!more) break;
            // ---- shift buffers ------------------------------------------
            va = nva; vb = nvb; lab = nlab;
            rp = nrp; lp = nlp; row0 = nrow;
        }
        row0 += lstep;    // position for tail check below
    }

    // odd-B tail: one row, h==0 half does the work (h==1 joins shuffles)
    if (row0 < B) {
        const float* trp = logits + (size_t)row0 * kC + c0;
        const int lab = __ldg(labels + row0);
        const float4 va = __ldg(reinterpret_cast<const float4*>(trp));
        const float4 vb = __ldg(reinterpret_cast<const float4*>(trp + 64));
        float e[8];
        e[0] = __expf(va.x); e[1] = __expf(va.y);
        e[2] = __expf(va.z); e[3] = __expf(va.w);
        e[4] = __expf(vb.x); e[5] = __expf(vb.y);
        e[6] = __expf(vb.z); e[7] = __expf(vb.w);
        float sm = 0.0f;
        #pragma unroll
        for (int j = 0; j < 8; j++) sm += e[j];
        #pragma unroll
        for (int o = 8; o > 0; o >>= 1)
            sm += __shfl_xor_sync(0xffffffffu, sm, o);
        if (h == 0) {
            const float inv = __fdividef(1.0f, sm);
            const int  r    = lab & 63;
            const int  jlab = (lab >> 6 << 2) | (r & 3);
            const bool match = (L == (r >> 2));
            #pragma unroll
            for (int j = 0; j < 8; j++) {
                const float p = e[j] * inv;
                int k = __float2int_ru(p * 15.0f) - 1;
                k = max(min(k, kBins - 1), 0);
                const bool isl = match && (j == jlab);
                const float add = isl ? (p - 1.0f) : p;
                const int cls = (j < 4) ? (c0 + j) : (64 + c0 + j - 4);
                atomicAdd(&s[cls * kBins + k], add);
            }
        }
    }

    // flush register accumulators into the block histogram
    #pragma unroll
    for (int j = 0; j < 8; j++) {
        const int cls = (j < 4) ? (c0 + j) : (64 + c0 + j - 4);
        atomicAdd(&s[cls * kBins], bin0[j]);
    }
    __syncthreads();

    // block histogram -> global
    for (int i = threadIdx.x; i < kSegs; i += blockDim.x) {
        const float v = s[i];
        if (v != 0.0f) atomicAdd(&g_seg[i], v);
    }

    // last-block finalize
    __shared__ bool isLast;
    __threadfence();
    if (threadIdx.x == 0)
        isLast = (atomicAdd(&g_count, 1u) == (unsigned)gridDim.x - 1u);
    __syncthreads();
    if (!isLast) return;

    __shared__ float red[32];
    float acc = 0.0f;
    for (int i = threadIdx.x; i < kSegs; i += blockDim.x) {
        acc += fabsf(__ldcg(&g_seg[i]));
        g_seg[i] = 0.0f;                   // reset for next replay
    }
    #pragma unroll
    for (int o = 16; o > 0; o >>= 1)
        acc += __shfl_xor_sync(0xffffffffu, acc, o);
    const int w = threadIdx.x >> 5;
    if (lane == 0) red[w] = acc;
    __syncthreads();
    if (w == 0) {
        const int nwarps = blockDim.x >> 5;
        acc = (lane < nwarps) ? red[lane] : 0.0f;
        #pragma unroll
        for (int o = 16; o > 0; o >>= 1)
            acc += __shfl_xor_sync(0xffffffffu, acc, o);
        if (threadIdx.x == 0) {
            out[0]  = acc * scale;
            g_count = 0u;                  // reset for next replay
        }
    }
}

extern "C" void kernel_launch(void* const* d_in, const int* in_sizes, int n_in,
                              void* d_out, int out_size) {
    const float* logits = (const float*)d_in[0];
    const int*   labels = (const int*)d_in[1];
    const int B = in_sizes[1];
    const float scale = 1.0f / ((float)B * (float)kC);
    sce_kernel<<<kBlocks, kThreads>>>(logits, labels, B, (float*)d_out, scale);
}

// round 13
// speedup vs baseline: 1.1301x; 1.0998x over previous
#include <cuda_runtime.h>

// SCE loss: softmax over C=128, signed per-(class,bin) histogram of
// p - onehot, then sum |.| / (B*C).
// Round 13: R8 skeleton + (a) pair-granular slow-path gates: 4 bodies
// guarded by pairwise max > t1 (23% entry each vs 65% for the 8-wide
// body) -> ~3x fewer predicated fixup slots and ATOMS issues; (b) label
// -1 via register byte-counters (no per-iteration atomic), corrected
// inside the rare pair body when the label element leaves bin 0.

namespace {
constexpr int kC       = 128;
constexpr int kBins    = 15;
constexpr int kSegs    = kC * kBins;   // 1920
constexpr int kBlocks  = 1184;
constexpr int kThreads = 256;
}

__device__ float    g_seg[kSegs];   // zero at load; last block re-zeroes
__device__ unsigned g_count;        // zero at load; last block re-zeroes

__global__ void __launch_bounds__(kThreads, 8)
sce_kernel(const float* __restrict__ logits, const int* __restrict__ labels,
           int B, float* __restrict__ out, float scale)
{
    __shared__ float s[kSegs];
    for (int i = threadIdx.x; i < kSegs; i += blockDim.x) s[i] = 0.0f;
    __syncthreads();

    const int lane = threadIdx.x & 31;
    const int wpb  = blockDim.x >> 5;
    const int gw   = blockIdx.x * wpb + (threadIdx.x >> 5);
    const int nw   = gridDim.x * wpb;
    const int h    = lane >> 4;          // which row of the pair
    const int L    = lane & 15;
    const int c0   = L << 2;             // classes c0..c0+3 and 64+c0..64+c0+3

    float bin0[8] = {0,0,0,0,0,0,0,0};
    int cnt0 = 0, cnt1 = 0;              // packed byte counts: label in bin0

    int row0 = gw * 2;
    const float* rp = logits + (size_t)(row0 + h) * kC + c0;
    const int*   lp = labels + row0 + h;
    const size_t rstep = (size_t)nw * 2 * kC;
    const int    lstep = nw * 2;

    for (; row0 + 1 < B; row0 += lstep, rp += rstep, lp += lstep) {
        const int lab = __ldg(lp);
        // both LDG.128s fully coalesced: 16 lanes x 16B contiguous per row
        const float4 va = __ldg(reinterpret_cast<const float4*>(rp));
        const float4 vb = __ldg(reinterpret_cast<const float4*>(rp + 64));

        float e[8];
        e[0] = __expf(va.x); e[1] = __expf(va.y);
        e[2] = __expf(va.z); e[3] = __expf(va.w);
        e[4] = __expf(vb.x); e[5] = __expf(vb.y);
        e[6] = __expf(vb.z); e[7] = __expf(vb.w);

        float sm = ((e[0] + e[1]) + (e[2] + e[3]))
                 + ((e[4] + e[5]) + (e[6] + e[7]));
        #pragma unroll
        for (int o = 8; o > 0; o >>= 1)      // 4-level, within 16-lane half
            sm += __shfl_xor_sync(0xffffffffu, sm, o);

        const float inv    = __fdividef(1.0f, sm);
        const float thresh = sm * (1.0f / 15.0f);   // e > thresh <=> p > 1/15

        #pragma unroll
        for (int j = 0; j < 8; j++)
            bin0[j] = fmaf(e[j], inv, bin0[j]);     // provisional bin 0

        // label -1: register byte-counter on the owning lane (no atomic)
        const int  r     = lab & 63;
        const bool match = (L == (r >> 2));
        const int  jlab  = ((lab >> 6) << 2) | (r & 3);
        if (match) {
            if (jlab < 4) cnt0 += 1 << (8 * jlab);
            else          cnt1 += 1 << (8 * (jlab - 4));
        }

        // pair-gated fixups: each gate covers 2 elements (entry ~23%)
        #pragma unroll
        for (int q = 0; q < 4; q++) {
            if (fmaxf(e[2 * q], e[2 * q + 1]) > thresh) {
                #pragma unroll
                for (int t = 0; t < 2; t++) {
                    const int j = 2 * q + t;
                    if (e[j] > thresh) {
                        const float p = e[j] * inv;
                        int k = __float2int_ru(p * 15.0f) - 1; // ceil(15p)-1
                        k = min(k, kBins - 1);
                        float add = p;
                        if (match && j == jlab) {   // -1 moves with label
                            add = p - 1.0f;
                            if (j < 4) cnt0 -= 1 << (8 * j);
                            else       cnt1 -= 1 << (8 * (j - 4));
                        }
                        const int cls = (j < 4) ? (c0 + j) : (64 + c0 + j - 4);
                        atomicAdd(&s[cls * kBins + k], add);
                        bin0[j] -= p;               // undo provisional add
                    }
                }
            }
        }
    }

    // odd-B tail: one row, h==0 half does the work (h==1 joins shuffles)
    if (row0 < B) {
        const float* trp = logits + (size_t)row0 * kC + c0;
        const int lab = __ldg(labels + row0);
        const float4 va = __ldg(reinterpret_cast<const float4*>(trp));
        const float4 vb = __ldg(reinterpret_cast<const float4*>(trp + 64));
        float e[8];
        e[0] = __expf(va.x); e[1] = __expf(va.y);
        e[2] = __expf(va.z); e[3] = __expf(va.w);
        e[4] = __expf(vb.x); e[5] = __expf(vb.y);
        e[6] = __expf(vb.z); e[7] = __expf(vb.w);
        float sm = 0.0f;
        #pragma unroll
        for (int j = 0; j < 8; j++) sm += e[j];
        #pragma unroll
        for (int o = 8; o > 0; o >>= 1)
            sm += __shfl_xor_sync(0xffffffffu, sm, o);
        if (h == 0) {
            const float inv = __fdividef(1.0f, sm);
            const int  r     = lab & 63;
            const bool match = (L == (r >> 2));
            const int  jlab  = ((lab >> 6) << 2) | (r & 3);
            #pragma unroll
            for (int j = 0; j < 8; j++) {
                const float p = e[j] * inv;
                int k = __float2int_ru(p * 15.0f) - 1;
                k = max(min(k, kBins - 1), 0);
                const bool isl = match && (j == jlab);
                const float add = isl ? (p - 1.0f) : p;
                const int cls = (j < 4) ? (c0 + j) : (64 + c0 + j - 4);
                atomicAdd(&s[cls * kBins + k], add);
            }
        }
    }

    // flush register accumulators into the block histogram
    #pragma unroll
    for (int j = 0; j < 8; j++) {
        const int lc = (j < 4) ? ((cnt0 >> (8 * j)) & 0xff)
                               : ((cnt1 >> (8 * (j - 4))) & 0xff);
        const int cls = (j < 4) ? (c0 + j) : (64 + c0 + j - 4);
        atomicAdd(&s[cls * kBins], bin0[j] - (float)lc);
    }
    __syncthreads();

    // block histogram -> global
    for (int i = threadIdx.x; i < kSegs; i += blockDim.x) {
        const float v = s[i];
        if (v != 0.0f) atomicAdd(&g_seg[i], v);
    }

    // last-block finalize
    __shared__ bool isLast;
    __threadfence();
    if (threadIdx.x == 0)
        isLast = (atomicAdd(&g_count, 1u) == (unsigned)gridDim.x - 1u);
    __syncthreads();
    if (!isLast) return;

    __shared__ float red[32];
    float acc = 0.0f;
    for (int i = threadIdx.x; i < kSegs; i += blockDim.x) {
        acc += fabsf(__ldcg(&g_seg[i]));
        g_seg[i] = 0.0f;                   // reset for next replay
    }
    #pragma unroll
    for (int o = 16; o > 0; o >>= 1)
        acc += __shfl_xor_sync(0xffffffffu, acc, o);
    const int w = threadIdx.x >> 5;
    if (lane == 0) red[w] = acc;
    __syncthreads();
    if (w == 0) {
        const int nwarps = blockDim.x >> 5;
        acc = (lane < nwarps) ? red[lane] : 0.0f;
        #pragma unroll
        for (int o = 16; o > 0; o >>= 1)
            acc += __shfl_xor_sync(0xffffffffu, acc, o);
        if (threadIdx.x == 0) {
            out[0]  = acc * scale;
            g_count = 0u;                  // reset for next replay
        }
    }
}

extern "C" void kernel_launch(void* const* d_in, const int* in_sizes, int n_in,
                              void* d_out, int out_size) {
    const float* logits = (const float*)d_in[0];
    const int*   labels = (const int*)d_in[1];
    const int B = in_sizes[1];
    const float scale = 1.0f / ((float)B * (float)kC);
    sce_kernel<<<kBlocks, kThreads>>>(logits, labels, B, (float*)d_out, scale);
}